// round 14
// baseline (speedup 1.0000x reference)
#include <cuda_runtime.h>
#include <cuda_bf16.h>
#include <mma.h>
#include <math.h>

using namespace nvcuda;

#define NN 50000
#define NN_PAD 50048          // padded rows so 128-row GEMM tiles never overflow
#define EE 500000
#define TOT (EE + NN)
#define HC 128
#define NB 49                 // ceil(NN/1024)
#define LDW 136               // smem leading dim (bf16 elems), 272B rows
#define MATS 34816            // 128*LDW*2 bytes per staged matrix (in elems: 128*LDW)

// ---------------- device scratch (16B-aligned) ----------------
__device__ __align__(16) float g_feat[NN * HC];
__device__ __align__(16) float g_xl[NN_PAD * HC];
__device__ __align__(16) float g_xr[NN_PAD * HC];
__device__ __align__(16) __nv_bfloat16 g_ahi[NN_PAD * HC];
__device__ __align__(16) __nv_bfloat16 g_alo[NN_PAD * HC];
__device__ __align__(16) __nv_bfloat16 g_whi[2 * HC * HC];
__device__ __align__(16) __nv_bfloat16 g_wlo[2 * HC * HC];
__device__ int g_rowptr[NN + 1];
__device__ int g_cursor[NN];
__device__ int g_deg[NN];
__device__ int g_col[TOT];
__device__ int g_bsum[NB];
__device__ int g_boff[NB];
__device__ int g_is64;

// ---------------- edge_index dtype detection ----------------
__global__ void k_detect(const void* __restrict__ ei) {
    if (threadIdx.x != 0 || blockIdx.x != 0) return;
    const long long* p = (const long long*)ei;
    int is64 = 1;
    for (int i = 0; i < 64; i++) {
        long long v = p[i];
        if (v < 0 || v >= (long long)NN) { is64 = 0; break; }
    }
    g_is64 = is64;
}

__device__ __forceinline__ int load_idx(const void* ei, int pos) {
    if (g_is64) return (int)((const long long*)ei)[pos];
    return ((const int*)ei)[pos];
}

// ---------------- CSR build ----------------
__global__ void k_zero_deg(int n) {
    int i = blockIdx.x * blockDim.x + threadIdx.x;
    if (i < n) g_deg[i] = 0;
}

__global__ void k_count(const void* __restrict__ ei, int e, int n) {
    int i = blockIdx.x * blockDim.x + threadIdx.x;
    int tot = e + n;
    if (i >= tot) return;
    int d = (i < e) ? load_idx(ei, e + i) : (i - e);
    if (d < 0 || d >= n) return;
    atomicAdd(&g_deg[d], 1);
}

__global__ void k_bsum(int n) {
    __shared__ int sh[256];
    int b = blockIdx.x;
    int lo = b * 1024, hi = min(n, lo + 1024);
    int s = 0;
    for (int i = lo + threadIdx.x; i < hi; i += 256) s += g_deg[i];
    sh[threadIdx.x] = s;
    __syncthreads();
    for (int off = 128; off > 0; off >>= 1) {
        if (threadIdx.x < off) sh[threadIdx.x] += sh[threadIdx.x + off];
        __syncthreads();
    }
    if (threadIdx.x == 0) g_bsum[b] = sh[0];
}

__global__ void k_bscan(int n) {
    if (threadIdx.x != 0) return;
    int acc = 0;
    for (int b = 0; b < NB; b++) { g_boff[b] = acc; acc += g_bsum[b]; }
    g_rowptr[n] = acc;
}

__global__ void k_scan3(int n) {
    __shared__ int sd[1024];
    int b = blockIdx.x;
    int tid = threadIdx.x;
    int i = b * 1024 + tid;
    int v = (i < n) ? g_deg[i] : 0;
    sd[tid] = v;
    __syncthreads();
    for (int off = 1; off < 1024; off <<= 1) {
        int t = (tid >= off) ? sd[tid - off] : 0;
        __syncthreads();
        sd[tid] += t;
        __syncthreads();
    }
    if (i < n) {
        int excl = g_boff[b] + sd[tid] - v;
        g_rowptr[i] = excl;
        g_cursor[i] = excl;
    }
}

__global__ void k_scatter(const void* __restrict__ ei, int e, int n) {
    int i = blockIdx.x * blockDim.x + threadIdx.x;
    int tot = e + n;
    if (i >= tot) return;
    int s, d;
    if (i < e) { s = load_idx(ei, i); d = load_idx(ei, e + i); }
    else       { s = i - e;           d = i - e; }
    if (d < 0 || d >= n || s < 0 || s >= n) return;
    int pos = atomicAdd(&g_cursor[d], 1);
    if (pos >= 0 && pos < TOT) g_col[pos] = s;
}

__global__ void k_sortseg(int n) {
    int i = blockIdx.x * blockDim.x + threadIdx.x;
    if (i >= n) return;
    int a = g_rowptr[i], b = g_rowptr[i + 1];
    for (int p = a + 1; p < b; p++) {
        int key = g_col[p];
        int q = p - 1;
        while (q >= a && g_col[q] > key) { g_col[q + 1] = g_col[q]; q--; }
        g_col[q + 1] = key;
    }
}

// ---------------- bf16 hi/lo split of activations (layer 0 input only) ---------
__global__ void k_split(const float* __restrict__ xext, int total4) {
    int i = blockIdx.x * blockDim.x + threadIdx.x;
    if (i >= total4) return;
    float4 v = ((const float4*)xext)[i];
    __nv_bfloat16 h0 = __float2bfloat16(v.x);
    __nv_bfloat16 h1 = __float2bfloat16(v.y);
    __nv_bfloat16 h2 = __float2bfloat16(v.z);
    __nv_bfloat16 h3 = __float2bfloat16(v.w);
    __nv_bfloat16 l0 = __float2bfloat16(v.x - __bfloat162float(h0));
    __nv_bfloat16 l1 = __float2bfloat16(v.y - __bfloat162float(h1));
    __nv_bfloat16 l2 = __float2bfloat16(v.z - __bfloat162float(h2));
    __nv_bfloat16 l3 = __float2bfloat16(v.w - __bfloat162float(h3));
    __nv_bfloat162* ph = (__nv_bfloat162*)g_ahi;
    __nv_bfloat162* pl = (__nv_bfloat162*)g_alo;
    ph[i * 2 + 0] = __nv_bfloat162(h0, h1);
    ph[i * 2 + 1] = __nv_bfloat162(h2, h3);
    pl[i * 2 + 0] = __nv_bfloat162(l0, l1);
    pl[i * 2 + 1] = __nv_bfloat162(l2, l3);
}

__global__ void k_splitW(const float* __restrict__ Wlp, const float* __restrict__ Wrp) {
    int i = blockIdx.x * blockDim.x + threadIdx.x;
    if (i >= 2 * HC * HC) return;
    const float* src = (i < HC * HC) ? Wlp : (Wrp - HC * HC);
    float v = src[i];
    __nv_bfloat16 h = __float2bfloat16(v);
    g_whi[i] = h;
    g_wlo[i] = __float2bfloat16(v - __bfloat162float(h));
}

// ---------------- WMMA split-bf16 GEMM v4 ----------------
// One block = 128 rows x BOTH projections (256 output cols). 512 threads /
// 16 warps, warp tile 32x64 (high smem arithmetic intensity). ALL operands
// staged in smem: Ah|Al + Wh/Wl for both projections = 6 x 34.8KB = 208.9KB.
// ONE barrier. C = Ahi@Whi + Alo@Whi + Ahi@Wlo (f32 accum).
__global__ __launch_bounds__(512) void k_wgemm4(int n) {
    extern __shared__ __align__(16) __nv_bfloat16 sh[];
    __nv_bfloat16* Ah = sh;
    __nv_bfloat16* Al = sh + 128 * LDW;
    __nv_bfloat16* Wm = sh + 2 * 128 * LDW;   // [Wh0, Wl0, Wh1, Wl1]
    int tid = threadIdx.x;
    int baser = blockIdx.x * 128;             // +127 < NN_PAD, unguarded

#pragma unroll
    for (int it = 0; it < 4; it++) {
        int idx = it * 512 + tid;
        int r = idx >> 4, c = (idx & 15) * 8;
        *(uint4*)(Ah + r * LDW + c) = *(const uint4*)(g_ahi + (size_t)(baser + r) * HC + c);
        *(uint4*)(Al + r * LDW + c) = *(const uint4*)(g_alo + (size_t)(baser + r) * HC + c);
        *(uint4*)(Wm + 0 * 128 * LDW + r * LDW + c) = *(const uint4*)(g_whi + r * HC + c);
        *(uint4*)(Wm + 1 * 128 * LDW + r * LDW + c) = *(const uint4*)(g_wlo + r * HC + c);
        *(uint4*)(Wm + 2 * 128 * LDW + r * LDW + c) = *(const uint4*)(g_whi + HC * HC + r * HC + c);
        *(uint4*)(Wm + 3 * 128 * LDW + r * LDW + c) = *(const uint4*)(g_wlo + HC * HC + r * HC + c);
    }
    __syncthreads();

    int warp = tid >> 5;
    int wrow = warp >> 2;        // 0..3 -> 32-row band
    int wc = warp & 3;           // 0..3 -> 64-col quarter of 256-wide output
    int wsel = wc >> 1;          // 0: Wl -> g_xl, 1: Wr -> g_xr
    int wn = wc & 1;             // 64-col half within projection
    const __nv_bfloat16* Wh = Wm + (wsel * 2 + 0) * 128 * LDW;
    const __nv_bfloat16* Wl = Wm + (wsel * 2 + 1) * 128 * LDW;

    wmma::fragment<wmma::accumulator, 16, 16, 16, float> acc[2][4];
#pragma unroll
    for (int i = 0; i < 2; i++)
#pragma unroll
        for (int j = 0; j < 4; j++) wmma::fill_fragment(acc[i][j], 0.f);

#pragma unroll
    for (int seg = 0; seg < 3; seg++) {
        const __nv_bfloat16* Ap = (seg == 1) ? Al : Ah;
        const __nv_bfloat16* Wp = (seg == 2) ? Wl : Wh;
#pragma unroll
        for (int k = 0; k < 128; k += 16) {
            wmma::fragment<wmma::matrix_a, 16, 16, 16, __nv_bfloat16, wmma::row_major> af[2];
#pragma unroll
            for (int i = 0; i < 2; i++)
                wmma::load_matrix_sync(af[i], Ap + (wrow * 32 + i * 16) * LDW + k, LDW);
#pragma unroll
            for (int j = 0; j < 4; j++) {
                wmma::fragment<wmma::matrix_b, 16, 16, 16, __nv_bfloat16, wmma::row_major> bf;
                wmma::load_matrix_sync(bf, Wp + k * LDW + wn * 64 + j * 16, LDW);
                wmma::mma_sync(acc[0][j], af[0], bf, acc[0][j]);
                wmma::mma_sync(acc[1][j], af[1], bf, acc[1][j]);
            }
        }
    }

    float* out = wsel ? g_xr : g_xl;
#pragma unroll
    for (int i = 0; i < 2; i++)
#pragma unroll
        for (int j = 0; j < 4; j++) {
            size_t row = baser + wrow * 32 + i * 16;
            wmma::store_matrix_sync(out + row * HC + wn * 64 + j * 16,
                                    acc[i][j], HC, wmma::mem_row_major);
        }
}

// ---------------- small GEMM: [n x 128] @ [128 x 16] (reads g_feat, fp32) -------
__global__ void k_gemm16(const float* __restrict__ W, int out_which, int n) {
    __shared__ float Ws[128 * 16];
    float* out = out_which ? g_xr : g_xl;
    int tid = threadIdx.x;
    for (int idx = tid; idx < 128 * 16; idx += 256) Ws[idx] = W[idx];
    __syncthreads();
    int j = tid & 15;
    int row = blockIdx.x * 16 + (tid >> 4);
    if (row >= n) return;
    const float4* a4 = (const float4*)(g_feat + (size_t)row * 128);
    float acc = 0.f;
#pragma unroll
    for (int k4 = 0; k4 < 32; k4++) {
        float4 av = a4[k4];
        acc += av.x * Ws[(k4 * 4 + 0) * 16 + j];
        acc += av.y * Ws[(k4 * 4 + 1) * 16 + j];
        acc += av.z * Ws[(k4 * 4 + 2) * 16 + j];
        acc += av.w * Ws[(k4 * 4 + 3) * 16 + j];
    }
    out[(size_t)row * 16 + j] = acc;
}

// ---------------- GATv2 layer, H=8 C=16 (HC=128), warp per dst node ------------
// mode bit0: write g_feat (fp32); mode bit1: write g_ahi/g_alo (fused split).
__global__ void k_gat128(const float* __restrict__ att, const float* __restrict__ bias,
                         const float* __restrict__ gam, const float* __restrict__ bet,
                         const float* __restrict__ mu, const float* __restrict__ vr,
                         int mode, int n) {
    int w = (blockIdx.x * blockDim.x + threadIdx.x) >> 5;
    int lane = threadIdx.x & 31;
    if (w >= n) return;
    int cb = lane * 4;
    float4 xrv = *(const float4*)(g_xr + (size_t)w * HC + cb);
    float4 atv = *(const float4*)(att + cb);
    float m = -INFINITY, den = 0.f;
    float4 acc = make_float4(0.f, 0.f, 0.f, 0.f);
    int p0 = g_rowptr[w], p1 = g_rowptr[w + 1];
    for (int p = p0; p < p1; p++) {
        int s = g_col[p];
        float4 v = *(const float4*)(g_xl + (size_t)s * HC + cb);
        float t0 = v.x + xrv.x, t1 = v.y + xrv.y, t2 = v.z + xrv.z, t3 = v.w + xrv.w;
        t0 = t0 > 0.f ? t0 : 0.2f * t0;
        t1 = t1 > 0.f ? t1 : 0.2f * t1;
        t2 = t2 > 0.f ? t2 : 0.2f * t2;
        t3 = t3 > 0.f ? t3 : 0.2f * t3;
        float part = t0 * atv.x + t1 * atv.y + t2 * atv.z + t3 * atv.w;
        part += __shfl_xor_sync(0xffffffffu, part, 1);
        part += __shfl_xor_sync(0xffffffffu, part, 2);   // 4-lane groups = one head
        float mn = fmaxf(m, part);
        float c  = __expf(m - mn);
        float wg = __expf(part - mn);
        den = den * c + wg;
        acc.x = acc.x * c + wg * v.x;
        acc.y = acc.y * c + wg * v.y;
        acc.z = acc.z * c + wg * v.z;
        acc.w = acc.w * c + wg * v.w;
        m = mn;
    }
    float inv = 1.f / den;
    float o[4];
    o[0] = acc.x * inv; o[1] = acc.y * inv; o[2] = acc.z * inv; o[3] = acc.w * inv;
#pragma unroll
    for (int j = 0; j < 4; j++) {
        int c = cb + j;
        float v = o[j] + bias[c];
        v = (v - mu[c]) * rsqrtf(vr[c] + 1e-5f) * gam[c] + bet[c];
        v = v > 0.f ? v : expm1f(v);
        o[j] = v;
    }
    if (mode & 1)
        *(float4*)(g_feat + (size_t)w * HC + cb) = make_float4(o[0], o[1], o[2], o[3]);
    if (mode & 2) {
        __nv_bfloat16 h[4], l[4];
#pragma unroll
        for (int j = 0; j < 4; j++) {
            h[j] = __float2bfloat16(o[j]);
            l[j] = __float2bfloat16(o[j] - __bfloat162float(h[j]));
        }
        __nv_bfloat162* ph = (__nv_bfloat162*)(g_ahi + (size_t)w * HC + cb);
        __nv_bfloat162* pl = (__nv_bfloat162*)(g_alo + (size_t)w * HC + cb);
        ph[0] = __nv_bfloat162(h[0], h[1]);
        ph[1] = __nv_bfloat162(h[2], h[3]);
        pl[0] = __nv_bfloat162(l[0], l[1]);
        pl[1] = __nv_bfloat162(l[2], l[3]);
    }
}

// ---------------- GATv2 final layer, H=1 C=16, warp per node -------------------
__global__ void k_gat16(const float* __restrict__ att, const float* __restrict__ bias,
                        float* __restrict__ out, int n) {
    int node = (blockIdx.x * blockDim.x + threadIdx.x) >> 5;
    int lane = threadIdx.x & 31;
    int ln = lane & 15;
    if (node >= n) return;
    float xrv = g_xr[(size_t)node * 16 + ln];
    float atv = att[ln];
    int p0 = g_rowptr[node], p1 = g_rowptr[node + 1];
    float m = -INFINITY, den = 0.f, accv = 0.f;
    for (int p = p0; p < p1; p++) {
        int s = g_col[p];
        float v = g_xl[(size_t)s * 16 + ln];
        float t = v + xrv;
        t = t > 0.f ? t : 0.2f * t;
        float part = t * atv;
        part += __shfl_xor_sync(0xffffffffu, part, 1);
        part += __shfl_xor_sync(0xffffffffu, part, 2);
        part += __shfl_xor_sync(0xffffffffu, part, 4);
        part += __shfl_xor_sync(0xffffffffu, part, 8);
        float mn = fmaxf(m, part);
        float c  = __expf(m - mn);
        float wg = __expf(part - mn);
        den = den * c + wg;
        accv = accv * c + wg * v;
        m = mn;
    }
    if (lane < 16) out[(size_t)node * 16 + ln] = accv / den + bias[ln];
}

// ---------------- host: kernel launches ONLY ----------------
extern "C" void kernel_launch(void* const* d_in, const int* in_sizes, int n_in,
                              void* d_out, int out_size) {
    const float* x  = (const float*)d_in[0];
    const void*  ei = d_in[1];
    const float* Wl[4] = { (const float*)d_in[2],  (const float*)d_in[6],
                           (const float*)d_in[10], (const float*)d_in[14] };
    const float* Wr[4] = { (const float*)d_in[3],  (const float*)d_in[7],
                           (const float*)d_in[11], (const float*)d_in[15] };
    const float* Aa[4] = { (const float*)d_in[4],  (const float*)d_in[8],
                           (const float*)d_in[12], (const float*)d_in[16] };
    const float* Bb[4] = { (const float*)d_in[5],  (const float*)d_in[9],
                           (const float*)d_in[13], (const float*)d_in[17] };
    const float* Gm[3] = { (const float*)d_in[18], (const float*)d_in[22], (const float*)d_in[26] };
    const float* Bt[3] = { (const float*)d_in[19], (const float*)d_in[23], (const float*)d_in[27] };
    const float* Mu[3] = { (const float*)d_in[20], (const float*)d_in[24], (const float*)d_in[28] };
    const float* Vv[3] = { (const float*)d_in[21], (const float*)d_in[25], (const float*)d_in[29] };

    int n = in_sizes[0] / HC;
    int e = in_sizes[1] / 2;
    int tot = e + n;
    int total4 = n * HC / 4;
    int gx = (n + 127) / 128;
    int smemBytes = 6 * 128 * LDW * 2;     // 208896 (A hi/lo + W hi/lo both proj)

    static int attr_done = 0;
    if (!attr_done) {
        cudaFuncSetAttribute(k_wgemm4, cudaFuncAttributeMaxDynamicSharedMemorySize, smemBytes);
        attr_done = 1;
    }

    // layer-0 projection first (no CSR dependency) -> k_wgemm4 is launch #4 (profiled)
    k_detect<<<1, 32>>>(ei);
    k_split<<<(total4 + 255) / 256, 256>>>(x, total4);
    k_splitW<<<(2 * HC * HC + 255) / 256, 256>>>(Wl[0], Wr[0]);
    k_wgemm4<<<gx, 512, smemBytes>>>(n);

    // CSR build (dst identical for all layers)
    k_zero_deg<<<(n + 255) / 256, 256>>>(n);
    k_count<<<(tot + 255) / 256, 256>>>(ei, e, n);
    k_bsum<<<NB, 256>>>(n);
    k_bscan<<<1, 32>>>(n);
    k_scan3<<<NB, 1024>>>(n);
    k_scatter<<<(tot + 255) / 256, 256>>>(ei, e, n);
    k_sortseg<<<(n + 255) / 256, 256>>>(n);

    // layer 0 aggregate: write split bf16 only (feeds layer-1 GEMM)
    k_gat128<<<(n + 7) / 8, 256>>>(Aa[0], Bb[0], Gm[0], Bt[0], Mu[0], Vv[0], 2, n);

    // layer 1
    k_splitW<<<(2 * HC * HC + 255) / 256, 256>>>(Wl[1], Wr[1]);
    k_wgemm4<<<gx, 512, smemBytes>>>(n);
    k_gat128<<<(n + 7) / 8, 256>>>(Aa[1], Bb[1], Gm[1], Bt[1], Mu[1], Vv[1], 2, n);

    // layer 2: write fp32 g_feat (feeds fp32 tail)
    k_splitW<<<(2 * HC * HC + 255) / 256, 256>>>(Wl[2], Wr[2]);
    k_wgemm4<<<gx, 512, smemBytes>>>(n);
    k_gat128<<<(n + 7) / 8, 256>>>(Aa[2], Bb[2], Gm[2], Bt[2], Mu[2], Vv[2], 1, n);

    // final layer: 128 -> 16, H=1, bias only (fp32, cheap)
    k_gemm16<<<(n + 15) / 16, 256>>>(Wl[3], 0, n);
    k_gemm16<<<(n + 15) / 16, 256>>>(Wr[3], 1, n);
    k_gat16<<<(n + 7) / 8, 256>>>(Aa[3], Bb[3], (float*)d_out, n);
}

// round 15
// speedup vs baseline: 4.4219x; 4.4219x over previous
#include <cuda_runtime.h>
#include <cuda_bf16.h>
#include <mma.h>
#include <math.h>

using namespace nvcuda;

#define NN 50000
#define NN_PAD 50048          // padded rows so 128-row GEMM tiles never overflow
#define EE 500000
#define TOT (EE + NN)
#define HC 128
#define NB 49                 // ceil(NN/1024)
#define LDW 136               // smem leading dim (bf16 elems), 272B rows

// ---------------- device scratch (16B-aligned) ----------------
__device__ __align__(16) float g_feat[NN * HC];
__device__ __align__(16) float g_xl[NN_PAD * HC];
__device__ __align__(16) float g_xr[NN_PAD * HC];
__device__ __align__(16) __nv_bfloat16 g_ahi[NN_PAD * HC];
__device__ __align__(16) __nv_bfloat16 g_alo[NN_PAD * HC];
__device__ __align__(16) __nv_bfloat16 g_whi[2 * HC * HC];
__device__ __align__(16) __nv_bfloat16 g_wlo[2 * HC * HC];
__device__ int g_rowptr[NN + 1];
__device__ int g_cursor[NN];
__device__ int g_deg[NN];
__device__ int g_col[TOT];
__device__ int g_bsum[NB];
__device__ int g_boff[NB];
__device__ int g_is64;

// ---------------- edge_index dtype detection ----------------
__global__ void k_detect(const void* __restrict__ ei) {
    if (threadIdx.x != 0 || blockIdx.x != 0) return;
    const long long* p = (const long long*)ei;
    int is64 = 1;
    for (int i = 0; i < 64; i++) {
        long long v = p[i];
        if (v < 0 || v >= (long long)NN) { is64 = 0; break; }
    }
    g_is64 = is64;
}

__device__ __forceinline__ int load_idx(const void* ei, int pos) {
    if (g_is64) return (int)((const long long*)ei)[pos];
    return ((const int*)ei)[pos];
}

// ---------------- CSR build ----------------
__global__ void k_zero_deg(int n) {
    int i = blockIdx.x * blockDim.x + threadIdx.x;
    if (i < n) g_deg[i] = 0;
}

__global__ void k_count(const void* __restrict__ ei, int e, int n) {
    int i = blockIdx.x * blockDim.x + threadIdx.x;
    int tot = e + n;
    if (i >= tot) return;
    int d = (i < e) ? load_idx(ei, e + i) : (i - e);
    if (d < 0 || d >= n) return;
    atomicAdd(&g_deg[d], 1);
}

__global__ void k_bsum(int n) {
    __shared__ int sh[256];
    int b = blockIdx.x;
    int lo = b * 1024, hi = min(n, lo + 1024);
    int s = 0;
    for (int i = lo + threadIdx.x; i < hi; i += 256) s += g_deg[i];
    sh[threadIdx.x] = s;
    __syncthreads();
    for (int off = 128; off > 0; off >>= 1) {
        if (threadIdx.x < off) sh[threadIdx.x] += sh[threadIdx.x + off];
        __syncthreads();
    }
    if (threadIdx.x == 0) g_bsum[b] = sh[0];
}

__global__ void k_bscan(int n) {
    if (threadIdx.x != 0) return;
    int acc = 0;
    for (int b = 0; b < NB; b++) { g_boff[b] = acc; acc += g_bsum[b]; }
    g_rowptr[n] = acc;
}

__global__ void k_scan3(int n) {
    __shared__ int sd[1024];
    int b = blockIdx.x;
    int tid = threadIdx.x;
    int i = b * 1024 + tid;
    int v = (i < n) ? g_deg[i] : 0;
    sd[tid] = v;
    __syncthreads();
    for (int off = 1; off < 1024; off <<= 1) {
        int t = (tid >= off) ? sd[tid - off] : 0;
        __syncthreads();
        sd[tid] += t;
        __syncthreads();
    }
    if (i < n) {
        int excl = g_boff[b] + sd[tid] - v;
        g_rowptr[i] = excl;
        g_cursor[i] = excl;
    }
}

__global__ void k_scatter(const void* __restrict__ ei, int e, int n) {
    int i = blockIdx.x * blockDim.x + threadIdx.x;
    int tot = e + n;
    if (i >= tot) return;
    int s, d;
    if (i < e) { s = load_idx(ei, i); d = load_idx(ei, e + i); }
    else       { s = i - e;           d = i - e; }
    if (d < 0 || d >= n || s < 0 || s >= n) return;
    int pos = atomicAdd(&g_cursor[d], 1);
    if (pos >= 0 && pos < TOT) g_col[pos] = s;
}

__global__ void k_sortseg(int n) {
    int i = blockIdx.x * blockDim.x + threadIdx.x;
    if (i >= n) return;
    int a = g_rowptr[i], b = g_rowptr[i + 1];
    for (int p = a + 1; p < b; p++) {
        int key = g_col[p];
        int q = p - 1;
        while (q >= a && g_col[q] > key) { g_col[q + 1] = g_col[q]; q--; }
        g_col[q + 1] = key;
    }
}

// ---------------- bf16 hi/lo split of activations (layer 0 input only) ---------
__global__ void k_split(const float* __restrict__ xext, int total4) {
    int i = blockIdx.x * blockDim.x + threadIdx.x;
    if (i >= total4) return;
    float4 v = ((const float4*)xext)[i];
    __nv_bfloat16 h0 = __float2bfloat16(v.x);
    __nv_bfloat16 h1 = __float2bfloat16(v.y);
    __nv_bfloat16 h2 = __float2bfloat16(v.z);
    __nv_bfloat16 h3 = __float2bfloat16(v.w);
    __nv_bfloat16 l0 = __float2bfloat16(v.x - __bfloat162float(h0));
    __nv_bfloat16 l1 = __float2bfloat16(v.y - __bfloat162float(h1));
    __nv_bfloat16 l2 = __float2bfloat16(v.z - __bfloat162float(h2));
    __nv_bfloat16 l3 = __float2bfloat16(v.w - __bfloat162float(h3));
    __nv_bfloat162* ph = (__nv_bfloat162*)g_ahi;
    __nv_bfloat162* pl = (__nv_bfloat162*)g_alo;
    ph[i * 2 + 0] = __nv_bfloat162(h0, h1);
    ph[i * 2 + 1] = __nv_bfloat162(h2, h3);
    pl[i * 2 + 0] = __nv_bfloat162(l0, l1);
    pl[i * 2 + 1] = __nv_bfloat162(l2, l3);
}

__global__ void k_splitW(const float* __restrict__ Wlp, const float* __restrict__ Wrp) {
    int i = blockIdx.x * blockDim.x + threadIdx.x;
    if (i >= 2 * HC * HC) return;
    const float* src = (i < HC * HC) ? Wlp : (Wrp - HC * HC);
    float v = src[i];
    __nv_bfloat16 h = __float2bfloat16(v);
    g_whi[i] = h;
    g_wlo[i] = __float2bfloat16(v - __bfloat162float(h));
}

// ---------------- WMMA split-bf16 GEMM (R10-proven config) ----------------
// 256 threads / 8 warps, warp tile 32x64. All operands in smem
// (Ah|Al|Wh|Wl = 139KB), ONE barrier. grid (ceil(n/128), 2); grid.y picks
// Wl->g_xl / Wr->g_xr. C = Ahi@Whi + Alo@Whi + Ahi@Wlo (f32 accum).
__global__ void k_wgemm(int n) {
    extern __shared__ __align__(16) __nv_bfloat16 sh[];
    __nv_bfloat16* Ah = sh;
    __nv_bfloat16* Al = sh + 128 * LDW;
    __nv_bfloat16* Wh = sh + 2 * 128 * LDW;
    __nv_bfloat16* Wl = sh + 3 * 128 * LDW;
    int tid = threadIdx.x;
    int baser = blockIdx.x * 128;             // +127 < NN_PAD, unguarded
    int wsel = blockIdx.y;
    const __nv_bfloat16* gWh = g_whi + wsel * HC * HC;
    const __nv_bfloat16* gWl = g_wlo + wsel * HC * HC;

#pragma unroll
    for (int it = 0; it < 8; it++) {
        int idx = it * 256 + tid;
        int r = idx >> 4, c = (idx & 15) * 8;
        *(uint4*)(Ah + r * LDW + c) = *(const uint4*)(g_ahi + (size_t)(baser + r) * HC + c);
        *(uint4*)(Al + r * LDW + c) = *(const uint4*)(g_alo + (size_t)(baser + r) * HC + c);
        *(uint4*)(Wh + r * LDW + c) = *(const uint4*)(gWh + r * HC + c);
        *(uint4*)(Wl + r * LDW + c) = *(const uint4*)(gWl + r * HC + c);
    }
    __syncthreads();

    int warp = tid >> 5;
    int wm = warp >> 1;          // 0..3 -> 32-row band
    int wn = warp & 1;           // 0..1 -> 64-col half

    wmma::fragment<wmma::accumulator, 16, 16, 16, float> acc[2][4];
#pragma unroll
    for (int i = 0; i < 2; i++)
#pragma unroll
        for (int j = 0; j < 4; j++) wmma::fill_fragment(acc[i][j], 0.f);

#pragma unroll
    for (int seg = 0; seg < 3; seg++) {
        const __nv_bfloat16* Ap = (seg == 1) ? Al : Ah;
        const __nv_bfloat16* Wp = (seg == 2) ? Wl : Wh;
#pragma unroll
        for (int k = 0; k < 128; k += 16) {
            wmma::fragment<wmma::matrix_a, 16, 16, 16, __nv_bfloat16, wmma::row_major> af[2];
            wmma::fragment<wmma::matrix_b, 16, 16, 16, __nv_bfloat16, wmma::row_major> bf[4];
#pragma unroll
            for (int i = 0; i < 2; i++)
                wmma::load_matrix_sync(af[i], Ap + (wm * 32 + i * 16) * LDW + k, LDW);
#pragma unroll
            for (int j = 0; j < 4; j++)
                wmma::load_matrix_sync(bf[j], Wp + k * LDW + wn * 64 + j * 16, LDW);
#pragma unroll
            for (int i = 0; i < 2; i++)
#pragma unroll
                for (int j = 0; j < 4; j++)
                    wmma::mma_sync(acc[i][j], af[i], bf[j], acc[i][j]);
        }
    }

    float* out = wsel ? g_xr : g_xl;
#pragma unroll
    for (int i = 0; i < 2; i++)
#pragma unroll
        for (int j = 0; j < 4; j++) {
            size_t row = baser + wm * 32 + i * 16;
            wmma::store_matrix_sync(out + row * HC + wn * 64 + j * 16,
                                    acc[i][j], HC, wmma::mem_row_major);
        }
}

// ---------------- small GEMM: [n x 128] @ [128 x 16] (reads g_feat, fp32) -------
__global__ void k_gemm16(const float* __restrict__ W, int out_which, int n) {
    __shared__ float Ws[128 * 16];
    float* out = out_which ? g_xr : g_xl;
    int tid = threadIdx.x;
    for (int idx = tid; idx < 128 * 16; idx += 256) Ws[idx] = W[idx];
    __syncthreads();
    int j = tid & 15;
    int row = blockIdx.x * 16 + (tid >> 4);
    if (row >= n) return;
    const float4* a4 = (const float4*)(g_feat + (size_t)row * 128);
    float acc = 0.f;
#pragma unroll
    for (int k4 = 0; k4 < 32; k4++) {
        float4 av = a4[k4];
        acc += av.x * Ws[(k4 * 4 + 0) * 16 + j];
        acc += av.y * Ws[(k4 * 4 + 1) * 16 + j];
        acc += av.z * Ws[(k4 * 4 + 2) * 16 + j];
        acc += av.w * Ws[(k4 * 4 + 3) * 16 + j];
    }
    out[(size_t)row * 16 + j] = acc;
}

// ---------------- GATv2 layer, H=8 C=16 (HC=128), warp per dst node ------------
// mode bit0: write g_feat (fp32); mode bit1: write g_ahi/g_alo (fused split).
__global__ void k_gat128(const float* __restrict__ att, const float* __restrict__ bias,
                         const float* __restrict__ gam, const float* __restrict__ bet,
                         const float* __restrict__ mu, const float* __restrict__ vr,
                         int mode, int n) {
    int w = (blockIdx.x * blockDim.x + threadIdx.x) >> 5;
    int lane = threadIdx.x & 31;
    if (w >= n) return;
    int cb = lane * 4;
    float4 xrv = *(const float4*)(g_xr + (size_t)w * HC + cb);
    float4 atv = *(const float4*)(att + cb);
    float m = -INFINITY, den = 0.f;
    float4 acc = make_float4(0.f, 0.f, 0.f, 0.f);
    int p0 = g_rowptr[w], p1 = g_rowptr[w + 1];
    for (int p = p0; p < p1; p++) {
        int s = g_col[p];
        float4 v = *(const float4*)(g_xl + (size_t)s * HC + cb);
        float t0 = v.x + xrv.x, t1 = v.y + xrv.y, t2 = v.z + xrv.z, t3 = v.w + xrv.w;
        t0 = t0 > 0.f ? t0 : 0.2f * t0;
        t1 = t1 > 0.f ? t1 : 0.2f * t1;
        t2 = t2 > 0.f ? t2 : 0.2f * t2;
        t3 = t3 > 0.f ? t3 : 0.2f * t3;
        float part = t0 * atv.x + t1 * atv.y + t2 * atv.z + t3 * atv.w;
        part += __shfl_xor_sync(0xffffffffu, part, 1);
        part += __shfl_xor_sync(0xffffffffu, part, 2);   // 4-lane groups = one head
        float mn = fmaxf(m, part);
        float c  = __expf(m - mn);
        float wg = __expf(part - mn);
        den = den * c + wg;
        acc.x = acc.x * c + wg * v.x;
        acc.y = acc.y * c + wg * v.y;
        acc.z = acc.z * c + wg * v.z;
        acc.w = acc.w * c + wg * v.w;
        m = mn;
    }
    float inv = 1.f / den;
    float o[4];
    o[0] = acc.x * inv; o[1] = acc.y * inv; o[2] = acc.z * inv; o[3] = acc.w * inv;
#pragma unroll
    for (int j = 0; j < 4; j++) {
        int c = cb + j;
        float v = o[j] + bias[c];
        v = (v - mu[c]) * rsqrtf(vr[c] + 1e-5f) * gam[c] + bet[c];
        v = v > 0.f ? v : expm1f(v);
        o[j] = v;
    }
    if (mode & 1)
        *(float4*)(g_feat + (size_t)w * HC + cb) = make_float4(o[0], o[1], o[2], o[3]);
    if (mode & 2) {
        __nv_bfloat16 h[4], l[4];
#pragma unroll
        for (int j = 0; j < 4; j++) {
            h[j] = __float2bfloat16(o[j]);
            l[j] = __float2bfloat16(o[j] - __bfloat162float(h[j]));
        }
        __nv_bfloat162* ph = (__nv_bfloat162*)(g_ahi + (size_t)w * HC + cb);
        __nv_bfloat162* pl = (__nv_bfloat162*)(g_alo + (size_t)w * HC + cb);
        ph[0] = __nv_bfloat162(h[0], h[1]);
        ph[1] = __nv_bfloat162(h[2], h[3]);
        pl[0] = __nv_bfloat162(l[0], l[1]);
        pl[1] = __nv_bfloat162(l[2], l[3]);
    }
}

// ---------------- GATv2 final layer, H=1 C=16, warp per node -------------------
__global__ void k_gat16(const float* __restrict__ att, const float* __restrict__ bias,
                        float* __restrict__ out, int n) {
    int node = (blockIdx.x * blockDim.x + threadIdx.x) >> 5;
    int lane = threadIdx.x & 31;
    int ln = lane & 15;
    if (node >= n) return;
    float xrv = g_xr[(size_t)node * 16 + ln];
    float atv = att[ln];
    int p0 = g_rowptr[node], p1 = g_rowptr[node + 1];
    float m = -INFINITY, den = 0.f, accv = 0.f;
    for (int p = p0; p < p1; p++) {
        int s = g_col[p];
        float v = g_xl[(size_t)s * 16 + ln];
        float t = v + xrv;
        t = t > 0.f ? t : 0.2f * t;
        float part = t * atv;
        part += __shfl_xor_sync(0xffffffffu, part, 1);
        part += __shfl_xor_sync(0xffffffffu, part, 2);
        part += __shfl_xor_sync(0xffffffffu, part, 4);
        part += __shfl_xor_sync(0xffffffffu, part, 8);
        float mn = fmaxf(m, part);
        float c  = __expf(m - mn);
        float wg = __expf(part - mn);
        den = den * c + wg;
        accv = accv * c + wg * v;
        m = mn;
    }
    if (lane < 16) out[(size_t)node * 16 + ln] = accv / den + bias[ln];
}

// ---------------- host: kernel launches ONLY ----------------
extern "C" void kernel_launch(void* const* d_in, const int* in_sizes, int n_in,
                              void* d_out, int out_size) {
    const float* x  = (const float*)d_in[0];
    const void*  ei = d_in[1];
    const float* Wl[4] = { (const float*)d_in[2],  (const float*)d_in[6],
                           (const float*)d_in[10], (const float*)d_in[14] };
    const float* Wr[4] = { (const float*)d_in[3],  (const float*)d_in[7],
                           (const float*)d_in[11], (const float*)d_in[15] };
    const float* Aa[4] = { (const float*)d_in[4],  (const float*)d_in[8],
                           (const float*)d_in[12], (const float*)d_in[16] };
    const float* Bb[4] = { (const float*)d_in[5],  (const float*)d_in[9],
                           (const float*)d_in[13], (const float*)d_in[17] };
    const float* Gm[3] = { (const float*)d_in[18], (const float*)d_in[22], (const float*)d_in[26] };
    const float* Bt[3] = { (const float*)d_in[19], (const float*)d_in[23], (const float*)d_in[27] };
    const float* Mu[3] = { (const float*)d_in[20], (const float*)d_in[24], (const float*)d_in[28] };
    const float* Vv[3] = { (const float*)d_in[21], (const float*)d_in[25], (const float*)d_in[29] };

    int n = in_sizes[0] / HC;
    int e = in_sizes[1] / 2;
    int tot = e + n;
    int total4 = n * HC / 4;
    int gx = (n + 127) / 128;
    int smemBytes = 4 * 128 * LDW * 2;     // 139264 (A hi/lo + W hi/lo)

    static int attr_done = 0;
    if (!attr_done) {
        cudaFuncSetAttribute(k_wgemm, cudaFuncAttributeMaxDynamicSharedMemorySize, smemBytes);
        attr_done = 1;
    }

    // layer-0 projection first (no CSR dependency) -> k_wgemm is launch #4 (profiled)
    k_detect<<<1, 32>>>(ei);
    k_split<<<(total4 + 255) / 256, 256>>>(x, total4);
    k_splitW<<<(2 * HC * HC + 255) / 256, 256>>>(Wl[0], Wr[0]);
    {
        dim3 grid(gx, 2);
        k_wgemm<<<grid, 256, smemBytes>>>(n);
    }

    // CSR build (dst identical for all layers)
    k_zero_deg<<<(n + 255) / 256, 256>>>(n);
    k_count<<<(tot + 255) / 256, 256>>>(ei, e, n);
    k_bsum<<<NB, 256>>>(n);
    k_bscan<<<1, 32>>>(n);
    k_scan3<<<NB, 1024>>>(n);
    k_scatter<<<(tot + 255) / 256, 256>>>(ei, e, n);
    k_sortseg<<<(n + 255) / 256, 256>>>(n);

    // layer 0 aggregate: write split bf16 only (feeds layer-1 GEMM)
    k_gat128<<<(n + 7) / 8, 256>>>(Aa[0], Bb[0], Gm[0], Bt[0], Mu[0], Vv[0], 2, n);

    // layer 1
    k_splitW<<<(2 * HC * HC + 255) / 256, 256>>>(Wl[1], Wr[1]);
    {
        dim3 grid(gx, 2);
        k_wgemm<<<grid, 256, smemBytes>>>(n);
    }
    k_gat128<<<(n + 7) / 8, 256>>>(Aa[1], Bb[1], Gm[1], Bt[1], Mu[1], Vv[1], 2, n);

    // layer 2: write fp32 g_feat (feeds fp32 tail)
    k_splitW<<<(2 * HC * HC + 255) / 256, 256>>>(Wl[2], Wr[2]);
    {
        dim3 grid(gx, 2);
        k_wgemm<<<grid, 256, smemBytes>>>(n);
    }
    k_gat128<<<(n + 7) / 8, 256>>>(Aa[2], Bb[2], Gm[2], Bt[2], Mu[2], Vv[2], 1, n);

    // final layer: 128 -> 16, H=1, bias only (fp32, cheap)
    k_gemm16<<<(n + 15) / 16, 256>>>(Wl[3], 0, n);
    k_gemm16<<<(n + 15) / 16, 256>>>(Wr[3], 1, n);
    k_gat16<<<(n + 7) / 8, 256>>>(Aa[3], Bb[3], (float*)d_out, n);
}